// round 6
// baseline (speedup 1.0000x reference)
#include <cuda_runtime.h>

#define OUT_DIM 4096
#define IN_DIM  8192
#define ALPHA   0.001f
#define EPS     1e-12f

// Scan-kernel geometry: 128x128 tiles, float4 access, chains of 32
#define TROWS   128
#define NTILES  (OUT_DIM / TROWS)     // 32 tiles per chain
#define CCOLS   128
#define NCHUNK  (IN_DIM / CCOLS)      // 64 independent chains
#define NSLOTS  (NTILES * NCHUNK)     // 2048 slots

// Scratch (allocation-free)
__device__ float g_y[OUT_DIM];
__device__ float g_yv[OUT_DIM];
__device__ float g_incl[NSLOTS * CCOLS];  // 1 MB, inclusive prefixes
__device__ int   g_flag[NSLOTS];          // 0 = pending, 2 = inclusive ready

__device__ __forceinline__ int ld_acquire(const int* p) {
    int v;
    asm volatile("ld.acquire.gpu.s32 %0, [%1];" : "=r"(v) : "l"(p));
    return v;
}
__device__ __forceinline__ void st_release(int* p, int v) {
    asm volatile("st.release.gpu.s32 [%0], %1;" :: "l"(p), "r"(v));
}

// ---------------------------------------------------------------------------
// Kernel 1: GEMV  y[r] = dot(W[r,:], x)
// ---------------------------------------------------------------------------
__global__ void __launch_bounds__(256) gemv_kernel(
    const float* __restrict__ W, const float* __restrict__ x, float* __restrict__ y)
{
    const int row = blockIdx.x;
    const int tid = threadIdx.x;
    const float4* Wr = reinterpret_cast<const float4*>(W + (size_t)row * IN_DIM);
    const float4* x4 = reinterpret_cast<const float4*>(x);

    float s = 0.0f;
#pragma unroll
    for (int i = tid; i < IN_DIM / 4; i += 256) {
        float4 w = __ldcs(&Wr[i]);
        float4 v = x4[i];
        s += w.x * v.x + w.y * v.y + w.z * v.z + w.w * v.w;
    }
#pragma unroll
    for (int o = 16; o > 0; o >>= 1) s += __shfl_down_sync(0xFFFFFFFFu, s, o);

    __shared__ float red[8];
    if ((tid & 31) == 0) red[tid >> 5] = s;
    __syncthreads();
    if (tid < 8) {
        s = red[tid];
#pragma unroll
        for (int o = 4; o > 0; o >>= 1) s += __shfl_down_sync(0xFFu, s, o);
        if (tid == 0) y[row] = s;
    }
}

// ---------------------------------------------------------------------------
// Kernel 2: normalize y -> yv, emit y_n, reset lookback flags (per replay)
// ---------------------------------------------------------------------------
__global__ void __launch_bounds__(1024) normalize_kernel(
    const float* __restrict__ y, float* __restrict__ yv, float* __restrict__ out_yn)
{
    const int tid = threadIdx.x;

#pragma unroll
    for (int i = tid; i < NSLOTS; i += 1024) g_flag[i] = 0;

    float ss = 0.0f;
#pragma unroll
    for (int i = tid; i < OUT_DIM; i += 1024) {
        float v = y[i];
        ss += v * v;
    }
#pragma unroll
    for (int o = 16; o > 0; o >>= 1) ss += __shfl_down_sync(0xFFFFFFFFu, ss, o);

    __shared__ float red[32];
    if ((tid & 31) == 0) red[tid >> 5] = ss;
    __syncthreads();
    __shared__ float s_inv;
    if (tid < 32) {
        float t = red[tid];
#pragma unroll
        for (int o = 16; o > 0; o >>= 1) t += __shfl_down_sync(0xFFFFFFFFu, t, o);
        if (tid == 0) s_inv = 1.0f / fmaxf(sqrtf(t), EPS);
    }
    __syncthreads();
    const float inv = s_inv;
#pragma unroll
    for (int i = tid; i < OUT_DIM; i += 1024) {
        float v = y[i] * inv;
        yv[i]     = v;
        out_yn[i] = v;
    }
}

// ---------------------------------------------------------------------------
// Kernel 3: single-pass lookback scan + Sanger apply.
// Tile 128x128, 8 warps x 16-row segments, lane <-> 4 columns.
// Warp 0 fetches the predecessor's inclusive prefix BEFORE the block barrier,
// overlapping the wait with the other warps' tile load. Flag protocol 0->2;
// lookback depth is exactly 1 (predecessor publishes full inclusive).
// ---------------------------------------------------------------------------
__global__ void __launch_bounds__(256) sanger_scan_kernel(
    const float* __restrict__ W, const float* __restrict__ x,
    const float* __restrict__ yv, float* __restrict__ Wout)
{
    __shared__ float4 Wsh[TROWS][CCOLS / 4];   // 64 KB
    __shared__ float  yvs[TROWS];              // 512 B
    __shared__ float4 s_part[8][CCOLS / 4];    // 4 KB
    __shared__ float4 excl_sh[CCOLS / 4];      // 512 B

    const int tid  = threadIdx.x;
    const int l    = tid & 31;                 // lane -> float4 column group
    const int w    = tid >> 5;                 // warp -> 16-row segment
    const int cc   = blockIdx.x;               // chain id (fastest)
    const int t    = blockIdx.y;               // tile / scan dim (slowest)
    const int row0 = t * TROWS;
    const int col0 = cc * CCOLS;
    const int slotbase = cc * NTILES;
    const int slot     = slotbase + t;

    if (tid < TROWS) yvs[tid] = yv[row0 + tid];

    // Load W tile: warp w loads rows w*16..w*16+15, lane l -> cols l*4..l*4+3
    {
        const float4* Wp = reinterpret_cast<const float4*>(
            W + (size_t)(row0 + w * 16) * IN_DIM + col0) + l;
#pragma unroll
        for (int j = 0; j < 16; ++j)
            Wsh[w * 16 + j][l] = __ldcs(Wp + (size_t)j * (IN_DIM / 4));
    }

    // Per-segment partials. Warp 0's own data is register/smem local; the
    // yvs staging needs a barrier ONLY for rows loaded by other warps, so
    // warp 0 computes from its own loads after a warp-local sync.
    __syncwarp();
    float4 P = make_float4(0.f, 0.f, 0.f, 0.f);
    {
        // yvs[w*16 + j] was written by threads of warp (w*16+j)/... careful:
        // yvs[tid<128] written by warps 0-3. Warp 0 reads yvs[0..15] -> its
        // own writes. Safe pre-barrier only for warp 0; other warps compute
        // after the block barrier below. To keep it simple and uniform, use
        // registers for the yv slice instead of smem for the partial.
        const float* yvp = yv + row0 + w * 16;
#pragma unroll
        for (int j = 0; j < 16; ++j) {
            const float4 wv = Wsh[w * 16 + j][l];
            const float  yj = __ldg(yvp + j);
            P.x += wv.x * yj; P.y += wv.y * yj; P.z += wv.z * yj; P.w += wv.w * yj;
        }
    }
    s_part[w][l] = P;

    // Warp 0: fetch predecessor's inclusive prefix (overlaps other warps'
    // outstanding loads; predecessor has smaller linear block id).
    if (w == 0) {
        float4 e = make_float4(0.f, 0.f, 0.f, 0.f);
        if (t > 0) {
            const int pslot = slot - 1;
            if (l == 0) {
                while (ld_acquire(&g_flag[pslot]) == 0) {}
            }
            __syncwarp();
            const float4* src = reinterpret_cast<const float4*>(
                g_incl + (size_t)pslot * CCOLS);
            e = __ldcs(src + l);
        }
        excl_sh[l] = e;
    }
    __syncthreads();

    // Warp 0: total aggregate + publish inclusive
    if (w == 0) {
        float4 agg = make_float4(0.f, 0.f, 0.f, 0.f);
#pragma unroll
        for (int ww = 0; ww < 8; ++ww) {
            const float4 p = s_part[ww][l];
            agg.x += p.x; agg.y += p.y; agg.z += p.z; agg.w += p.w;
        }
        const float4 e = excl_sh[l];
        float4* inclp = reinterpret_cast<float4*>(g_incl + (size_t)slot * CCOLS);
        inclp[l] = make_float4(e.x + agg.x, e.y + agg.y, e.z + agg.z, e.w + agg.w);
        __syncwarp();
        if (l == 0) { __threadfence(); st_release(&g_flag[slot], 2); }
    }
    __syncthreads();

    // In-block segment exclusive prefix
    float4 run = excl_sh[l];
#pragma unroll
    for (int ww = 0; ww < 8; ++ww)
        if (ww < w) {
            const float4 p = s_part[ww][l];
            run.x += p.x; run.y += p.y; run.z += p.z; run.w += p.w;
        }

    // Apply + streaming store
    const float4 xc = reinterpret_cast<const float4*>(x + col0)[l];
    {
        float4* Op = reinterpret_cast<float4*>(
            Wout + (size_t)(row0 + w * 16) * IN_DIM + col0) + l;
#pragma unroll
        for (int j = 0; j < 16; ++j) {
            const int r = w * 16 + j;
            const float4 wv = Wsh[r][l];
            const float  yj = yvs[r];
            run.x += wv.x * yj; run.y += wv.y * yj;
            run.z += wv.z * yj; run.w += wv.w * yj;
            float4 o;
            const float a = ALPHA * yj;
            o.x = wv.x + a * (xc.x - run.x);
            o.y = wv.y + a * (xc.y - run.y);
            o.z = wv.z + a * (xc.z - run.z);
            o.w = wv.w + a * (xc.w - run.w);
            __stcs(Op + (size_t)j * (IN_DIM / 4), o);
        }
    }
}

// ---------------------------------------------------------------------------
extern "C" void kernel_launch(void* const* d_in, const int* in_sizes, int n_in,
                              void* d_out, int out_size)
{
    const float* x = (const float*)d_in[0];  // [1, 8192]
    const float* W = (const float*)d_in[1];  // [4096, 8192]
    float* out = (float*)d_out;              // [4096 y_n] ++ [4096*8192 W_new]

    float* y  = nullptr;
    float* yv = nullptr;
    cudaGetSymbolAddress((void**)&y,  g_y);
    cudaGetSymbolAddress((void**)&yv, g_yv);

    gemv_kernel<<<OUT_DIM, 256>>>(W, x, y);
    normalize_kernel<<<1, 1024>>>(y, yv, out);

    dim3 grid(NCHUNK, NTILES);   // chain id fastest; scan dim t SLOWEST
    sanger_scan_kernel<<<grid, 256>>>(W, x, yv, out + OUT_DIM);
}

// round 7
// speedup vs baseline: 1.1549x; 1.1549x over previous
#include <cuda_runtime.h>

#define OUT_DIM 4096
#define IN_DIM  8192
#define ALPHA   0.001f
#define EPS     1e-12f

// Scan-kernel geometry: 128x128 tiles, float4 access, chains of 32
#define TROWS   128
#define NTILES  (OUT_DIM / TROWS)     // 32 tiles per chain
#define CCOLS   128
#define NCHUNK  (IN_DIM / CCOLS)      // 64 independent chains
#define NSLOTS  (NTILES * NCHUNK)     // 2048 slots

// Scratch (allocation-free)
__device__ float g_y[OUT_DIM];
__device__ float g_yv[OUT_DIM];
__device__ float g_agg[NSLOTS * CCOLS];   // 1 MB
__device__ float g_incl[NSLOTS * CCOLS];  // 1 MB
__device__ int   g_flag[NSLOTS];

__device__ __forceinline__ int ld_acquire(const int* p) {
    int v;
    asm volatile("ld.acquire.gpu.s32 %0, [%1];" : "=r"(v) : "l"(p));
    return v;
}
__device__ __forceinline__ void st_release(int* p, int v) {
    asm volatile("st.release.gpu.s32 [%0], %1;" :: "l"(p), "r"(v));
}

// ---------------------------------------------------------------------------
// Kernel 1: GEMV  y[r] = dot(W[r,:], x).
// DEFAULT cache policy on W: deliberately leave W resident in L2 (~126 MB)
// so the scan kernel re-reads it from L2 instead of DRAM.
// ---------------------------------------------------------------------------
__global__ void __launch_bounds__(256) gemv_kernel(
    const float* __restrict__ W, const float* __restrict__ x, float* __restrict__ y)
{
    const int row = blockIdx.x;
    const int tid = threadIdx.x;
    const float4* Wr = reinterpret_cast<const float4*>(W + (size_t)row * IN_DIM);
    const float4* x4 = reinterpret_cast<const float4*>(x);

    float s = 0.0f;
#pragma unroll
    for (int i = tid; i < IN_DIM / 4; i += 256) {
        float4 w = Wr[i];
        float4 v = x4[i];
        s += w.x * v.x + w.y * v.y + w.z * v.z + w.w * v.w;
    }
#pragma unroll
    for (int o = 16; o > 0; o >>= 1) s += __shfl_down_sync(0xFFFFFFFFu, s, o);

    __shared__ float red[8];
    if ((tid & 31) == 0) red[tid >> 5] = s;
    __syncthreads();
    if (tid < 8) {
        s = red[tid];
#pragma unroll
        for (int o = 4; o > 0; o >>= 1) s += __shfl_down_sync(0xFFu, s, o);
        if (tid == 0) y[row] = s;
    }
}

// ---------------------------------------------------------------------------
// Kernel 2: normalize y -> yv, emit y_n, reset lookback flags (per replay)
// ---------------------------------------------------------------------------
__global__ void __launch_bounds__(1024) normalize_kernel(
    const float* __restrict__ y, float* __restrict__ yv, float* __restrict__ out_yn)
{
    const int tid = threadIdx.x;

#pragma unroll
    for (int i = tid; i < NSLOTS; i += 1024) g_flag[i] = 0;

    float ss = 0.0f;
#pragma unroll
    for (int i = tid; i < OUT_DIM; i += 1024) {
        float v = y[i];
        ss += v * v;
    }
#pragma unroll
    for (int o = 16; o > 0; o >>= 1) ss += __shfl_down_sync(0xFFFFFFFFu, ss, o);

    __shared__ float red[32];
    if ((tid & 31) == 0) red[tid >> 5] = ss;
    __syncthreads();
    __shared__ float s_inv;
    if (tid < 32) {
        float t = red[tid];
#pragma unroll
        for (int o = 16; o > 0; o >>= 1) t += __shfl_down_sync(0xFFFFFFFFu, t, o);
        if (tid == 0) s_inv = 1.0f / fmaxf(sqrtf(t), EPS);
    }
    __syncthreads();
    const float inv = s_inv;
#pragma unroll
    for (int i = tid; i < OUT_DIM; i += 1024) {
        float v = y[i] * inv;
        yv[i]     = v;
        out_yn[i] = v;
    }
}

// ---------------------------------------------------------------------------
// Kernel 3: single-pass decoupled-lookback scan + Sanger apply.
// (Round-5 protocol: parallel aggregate publication + serial-walk lookback.)
// W reads use DEFAULT policy -> served mostly from L2 left warm by gemv.
// Wout writes use .cs (evict-first) so the streamed output does not displace W.
// ---------------------------------------------------------------------------
__global__ void __launch_bounds__(256) sanger_scan_kernel(
    const float* __restrict__ W, const float* __restrict__ x,
    const float* __restrict__ yv, float* __restrict__ Wout)
{
    __shared__ float4 Wsh[TROWS][CCOLS / 4];   // 64 KB
    __shared__ float  yvs[TROWS];              // 512 B
    __shared__ float4 s_part[8][CCOLS / 4];    // 4 KB
    __shared__ float4 excl_sh[CCOLS / 4];      // 512 B

    const int tid  = threadIdx.x;
    const int l    = tid & 31;                 // lane -> float4 column group
    const int w    = tid >> 5;                 // warp -> 16-row segment
    const int cc   = blockIdx.x;               // chain id (fastest)
    const int t    = blockIdx.y;               // tile / scan dim (slowest)
    const int row0 = t * TROWS;
    const int col0 = cc * CCOLS;
    const int slotbase = cc * NTILES;
    const int slot     = slotbase + t;

    if (tid < TROWS) yvs[tid] = yv[row0 + tid];

    // Load W tile: warp w loads rows w*16..w*16+15, lane l -> cols l*4..l*4+3
    {
        const float4* Wp = reinterpret_cast<const float4*>(
            W + (size_t)(row0 + w * 16) * IN_DIM + col0) + l;
#pragma unroll
        for (int j = 0; j < 16; ++j)
            Wsh[w * 16 + j][l] = Wp[(size_t)j * (IN_DIM / 4)];
    }
    __syncthreads();

    // Per-segment column partials (4 independent accumulators per thread)
    float4 P = make_float4(0.f, 0.f, 0.f, 0.f);
#pragma unroll
    for (int j = 0; j < 16; ++j) {
        const float4 wv = Wsh[w * 16 + j][l];
        const float  yj = yvs[w * 16 + j];
        P.x += wv.x * yj; P.y += wv.y * yj; P.z += wv.z * yj; P.w += wv.w * yj;
    }
    s_part[w][l] = P;
    __syncthreads();

    // Warp 0: publish aggregate, lookback, publish inclusive
    if (w == 0) {
        float4 agg = make_float4(0.f, 0.f, 0.f, 0.f);
#pragma unroll
        for (int ww = 0; ww < 8; ++ww) {
            const float4 p = s_part[ww][l];
            agg.x += p.x; agg.y += p.y; agg.z += p.z; agg.w += p.w;
        }

        float4* aggp  = reinterpret_cast<float4*>(g_agg  + (size_t)slot * CCOLS);
        float4* inclp = reinterpret_cast<float4*>(g_incl + (size_t)slot * CCOLS);

        float4 e = make_float4(0.f, 0.f, 0.f, 0.f);
        if (t == 0) {
            inclp[l] = agg;
            __syncwarp();
            if (l == 0) { __threadfence(); st_release(&g_flag[slot], 2); }
        } else {
            aggp[l] = agg;
            __syncwarp();
            if (l == 0) { __threadfence(); st_release(&g_flag[slot], 1); }

            int p = t - 1;
            while (true) {
                int f;
                do { f = ld_acquire(&g_flag[slotbase + p]); } while (f == 0);
                const float4* src = reinterpret_cast<const float4*>(
                    ((f == 2) ? g_incl : g_agg) + (size_t)(slotbase + p) * CCOLS);
                const float4 v = src[l];
                e.x += v.x; e.y += v.y; e.z += v.z; e.w += v.w;
                if (f == 2 || --p < 0) break;
            }
            float4 inc = make_float4(e.x + agg.x, e.y + agg.y, e.z + agg.z, e.w + agg.w);
            inclp[l] = inc;
            __syncwarp();
            if (l == 0) { __threadfence(); st_release(&g_flag[slot], 2); }
        }
        excl_sh[l] = e;
    }
    __syncthreads();

    // In-block segment exclusive prefix
    float4 run = excl_sh[l];
#pragma unroll
    for (int ww = 0; ww < 8; ++ww)
        if (ww < w) {
            const float4 p = s_part[ww][l];
            run.x += p.x; run.y += p.y; run.z += p.z; run.w += p.w;
        }

    // Apply + streaming store (evict-first: never re-read)
    const float4 xc = reinterpret_cast<const float4*>(x + col0)[l];
    {
        float4* Op = reinterpret_cast<float4*>(
            Wout + (size_t)(row0 + w * 16) * IN_DIM + col0) + l;
#pragma unroll
        for (int j = 0; j < 16; ++j) {
            const int r = w * 16 + j;
            const float4 wv = Wsh[r][l];
            const float  yj = yvs[r];
            run.x += wv.x * yj; run.y += wv.y * yj;
            run.z += wv.z * yj; run.w += wv.w * yj;
            float4 o;
            const float a = ALPHA * yj;
            o.x = wv.x + a * (xc.x - run.x);
            o.y = wv.y + a * (xc.y - run.y);
            o.z = wv.z + a * (xc.z - run.z);
            o.w = wv.w + a * (xc.w - run.w);
            __stcs(Op + (size_t)j * (IN_DIM / 4), o);
        }
    }
}

// ---------------------------------------------------------------------------
extern "C" void kernel_launch(void* const* d_in, const int* in_sizes, int n_in,
                              void* d_out, int out_size)
{
    const float* x = (const float*)d_in[0];  // [1, 8192]
    const float* W = (const float*)d_in[1];  // [4096, 8192]
    float* out = (float*)d_out;              // [4096 y_n] ++ [4096*8192 W_new]

    float* y  = nullptr;
    float* yv = nullptr;
    cudaGetSymbolAddress((void**)&y,  g_y);
    cudaGetSymbolAddress((void**)&yv, g_yv);

    gemv_kernel<<<OUT_DIM, 256>>>(W, x, y);
    normalize_kernel<<<1, 1024>>>(y, yv, out);

    dim3 grid(NCHUNK, NTILES);   // chain id fastest; scan dim t SLOWEST
    sanger_scan_kernel<<<grid, 256>>>(W, x, yv, out + OUT_DIM);
}

// round 8
// speedup vs baseline: 1.1569x; 1.0017x over previous
#include <cuda_runtime.h>

#define OUT_DIM 4096
#define IN_DIM  8192
#define ALPHA   0.001f
#define EPS     1e-12f

// Scan geometry: 64x128 tiles, W in registers, chains of 64
#define TROWS   64
#define NTILES  (OUT_DIM / TROWS)     // 64 tiles per chain
#define CCOLS   128
#define NCHUNK  (IN_DIM / CCOLS)      // 64 independent chains
#define NSLOTS  (NTILES * NCHUNK)     // 4096 slots

// Scratch (allocation-free)
__device__ float g_y[OUT_DIM];
__device__ float g_yv[OUT_DIM];
__device__ float g_agg[NSLOTS * CCOLS];   // 2 MB
__device__ float g_incl[NSLOTS * CCOLS];  // 2 MB
__device__ int   g_flag[NSLOTS];

__device__ __forceinline__ int ld_acquire(const int* p) {
    int v;
    asm volatile("ld.acquire.gpu.s32 %0, [%1];" : "=r"(v) : "l"(p));
    return v;
}
__device__ __forceinline__ void st_release(int* p, int v) {
    asm volatile("st.release.gpu.s32 [%0], %1;" :: "l"(p), "r"(v));
}

// ---------------------------------------------------------------------------
// Kernel 1: GEMV  y[r] = dot(W[r,:], x)   (.cs streaming reads — best measured)
// ---------------------------------------------------------------------------
__global__ void __launch_bounds__(256) gemv_kernel(
    const float* __restrict__ W, const float* __restrict__ x, float* __restrict__ y)
{
    const int row = blockIdx.x;
    const int tid = threadIdx.x;
    const float4* Wr = reinterpret_cast<const float4*>(W + (size_t)row * IN_DIM);
    const float4* x4 = reinterpret_cast<const float4*>(x);

    float s = 0.0f;
#pragma unroll
    for (int i = tid; i < IN_DIM / 4; i += 256) {
        float4 w = __ldcs(&Wr[i]);
        float4 v = x4[i];
        s += w.x * v.x + w.y * v.y + w.z * v.z + w.w * v.w;
    }
#pragma unroll
    for (int o = 16; o > 0; o >>= 1) s += __shfl_down_sync(0xFFFFFFFFu, s, o);

    __shared__ float red[8];
    if ((tid & 31) == 0) red[tid >> 5] = s;
    __syncthreads();
    if (tid < 8) {
        s = red[tid];
#pragma unroll
        for (int o = 4; o > 0; o >>= 1) s += __shfl_down_sync(0xFFu, s, o);
        if (tid == 0) y[row] = s;
    }
}

// ---------------------------------------------------------------------------
// Kernel 2: normalize y -> yv, emit y_n, reset lookback flags (per replay)
// ---------------------------------------------------------------------------
__global__ void __launch_bounds__(1024) normalize_kernel(
    const float* __restrict__ y, float* __restrict__ yv, float* __restrict__ out_yn)
{
    const int tid = threadIdx.x;

#pragma unroll
    for (int i = tid; i < NSLOTS; i += 1024) g_flag[i] = 0;

    float ss = 0.0f;
#pragma unroll
    for (int i = tid; i < OUT_DIM; i += 1024) {
        float v = y[i];
        ss += v * v;
    }
#pragma unroll
    for (int o = 16; o > 0; o >>= 1) ss += __shfl_down_sync(0xFFFFFFFFu, ss, o);

    __shared__ float red[32];
    if ((tid & 31) == 0) red[tid >> 5] = ss;
    __syncthreads();
    __shared__ float s_inv;
    if (tid < 32) {
        float t = red[tid];
#pragma unroll
        for (int o = 16; o > 0; o >>= 1) t += __shfl_down_sync(0xFFFFFFFFu, t, o);
        if (tid == 0) s_inv = 1.0f / fmaxf(sqrtf(t), EPS);
    }
    __syncthreads();
    const float inv = s_inv;
#pragma unroll
    for (int i = tid; i < OUT_DIM; i += 1024) {
        float v = y[i] * inv;
        yv[i]     = v;
        out_yn[i] = v;
    }
}

// ---------------------------------------------------------------------------
// Kernel 3: single-pass decoupled-lookback scan + Sanger apply.
// Tile 64 rows x 128 cols; 8 warps x 8-row segments; lane <-> 4 columns.
// W tile lives ENTIRELY in registers (8 float4/thread) — no smem staging,
// no load barrier, ~4.5 KB smem -> 4 blocks/SM.
// Round-5 two-flag protocol (parallel aggregate publication).
// ---------------------------------------------------------------------------
__global__ void __launch_bounds__(256, 4) sanger_scan_kernel(
    const float* __restrict__ W, const float* __restrict__ x,
    const float* __restrict__ yv, float* __restrict__ Wout)
{
    __shared__ float4 s_part[8][CCOLS / 4];    // 4 KB
    __shared__ float4 excl_sh[CCOLS / 4];      // 512 B

    const int tid  = threadIdx.x;
    const int l    = tid & 31;                 // lane -> float4 column group
    const int w    = tid >> 5;                 // warp -> 8-row segment
    const int cc   = blockIdx.x;               // chain id (fastest)
    const int t    = blockIdx.y;               // tile / scan dim (slowest)
    const int row0 = t * TROWS;
    const int col0 = cc * CCOLS;
    const int slotbase = cc * NTILES;
    const int slot     = slotbase + t;

    // yv values for this warp's 8 rows (uniform across warp -> broadcast)
    float yj[8];
    {
        const float* yvp = yv + row0 + w * 8;
#pragma unroll
        for (int j = 0; j < 8; ++j) yj[j] = __ldg(yvp + j);
    }

    // Load this thread's 8 rows x 4 cols of W into registers
    float4 Wr[8];
    {
        const float4* Wp = reinterpret_cast<const float4*>(
            W + (size_t)(row0 + w * 8) * IN_DIM + col0) + l;
#pragma unroll
        for (int j = 0; j < 8; ++j)
            Wr[j] = __ldcs(Wp + (size_t)j * (IN_DIM / 4));
    }

    // Per-segment column partials
    float4 P = make_float4(0.f, 0.f, 0.f, 0.f);
#pragma unroll
    for (int j = 0; j < 8; ++j) {
        P.x += Wr[j].x * yj[j]; P.y += Wr[j].y * yj[j];
        P.z += Wr[j].z * yj[j]; P.w += Wr[j].w * yj[j];
    }
    s_part[w][l] = P;
    __syncthreads();

    // Warp 0: publish aggregate, lookback, publish inclusive (two-flag protocol)
    if (w == 0) {
        float4 agg = make_float4(0.f, 0.f, 0.f, 0.f);
#pragma unroll
        for (int ww = 0; ww < 8; ++ww) {
            const float4 p = s_part[ww][l];
            agg.x += p.x; agg.y += p.y; agg.z += p.z; agg.w += p.w;
        }

        float4* aggp  = reinterpret_cast<float4*>(g_agg  + (size_t)slot * CCOLS);
        float4* inclp = reinterpret_cast<float4*>(g_incl + (size_t)slot * CCOLS);

        float4 e = make_float4(0.f, 0.f, 0.f, 0.f);
        if (t == 0) {
            inclp[l] = agg;
            __syncwarp();
            if (l == 0) { __threadfence(); st_release(&g_flag[slot], 2); }
        } else {
            aggp[l] = agg;
            __syncwarp();
            if (l == 0) { __threadfence(); st_release(&g_flag[slot], 1); }

            int p = t - 1;
            while (true) {
                int f;
                do { f = ld_acquire(&g_flag[slotbase + p]); } while (f == 0);
                const float4* src = reinterpret_cast<const float4*>(
                    ((f == 2) ? g_incl : g_agg) + (size_t)(slotbase + p) * CCOLS);
                const float4 v = src[l];
                e.x += v.x; e.y += v.y; e.z += v.z; e.w += v.w;
                if (f == 2 || --p < 0) break;
            }
            float4 inc = make_float4(e.x + agg.x, e.y + agg.y, e.z + agg.z, e.w + agg.w);
            inclp[l] = inc;
            __syncwarp();
            if (l == 0) { __threadfence(); st_release(&g_flag[slot], 2); }
        }
        excl_sh[l] = e;
    }
    __syncthreads();

    // In-block segment exclusive prefix
    float4 run = excl_sh[l];
#pragma unroll
    for (int ww = 0; ww < 8; ++ww)
        if (ww < w) {
            const float4 p = s_part[ww][l];
            run.x += p.x; run.y += p.y; run.z += p.z; run.w += p.w;
        }

    // Apply + streaming store (from registers)
    const float4 xc = reinterpret_cast<const float4*>(x + col0)[l];
    {
        float4* Op = reinterpret_cast<float4*>(
            Wout + (size_t)(row0 + w * 8) * IN_DIM + col0) + l;
#pragma unroll
        for (int j = 0; j < 8; ++j) {
            run.x += Wr[j].x * yj[j]; run.y += Wr[j].y * yj[j];
            run.z += Wr[j].z * yj[j]; run.w += Wr[j].w * yj[j];
            float4 o;
            const float a = ALPHA * yj[j];
            o.x = Wr[j].x + a * (xc.x - run.x);
            o.y = Wr[j].y + a * (xc.y - run.y);
            o.z = Wr[j].z + a * (xc.z - run.z);
            o.w = Wr[j].w + a * (xc.w - run.w);
            __stcs(Op + (size_t)j * (IN_DIM / 4), o);
        }
    }
}

// ---------------------------------------------------------------------------
extern "C" void kernel_launch(void* const* d_in, const int* in_sizes, int n_in,
                              void* d_out, int out_size)
{
    const float* x = (const float*)d_in[0];  // [1, 8192]
    const float* W = (const float*)d_in[1];  // [4096, 8192]
    float* out = (float*)d_out;              // [4096 y_n] ++ [4096*8192 W_new]

    float* y  = nullptr;
    float* yv = nullptr;
    cudaGetSymbolAddress((void**)&y,  g_y);
    cudaGetSymbolAddress((void**)&yv, g_yv);

    gemv_kernel<<<OUT_DIM, 256>>>(W, x, y);
    normalize_kernel<<<1, 1024>>>(y, yv, out);

    dim3 grid(NCHUNK, NTILES);   // chain id fastest; scan dim t SLOWEST
    sanger_scan_kernel<<<grid, 256>>>(W, x, yv, out + OUT_DIM);
}